// round 6
// baseline (speedup 1.0000x reference)
#include <cuda_runtime.h>

// Fixed shapes
#define KDIM   51
#define KP     52                // padded K (row 51 = ones, carries EPS exactly)
#define BDIM   256
#define CCOLS  24576             // 8192 points * 3
#define TCOLS  96                // columns per gram block (32 per d)
#define GBLKS  256               // gram blocks; 2/SM co-resident (<= 296 slots)
#define QBLKS  32                // blocks that continue into the quad phase
#define COLS_D 32                // columns per d per block
#define CPAD   56                // padded k-extent (multiple of 4 for LDS.128)
#define NTILE  13                // 52/4 k-tiles
#define NPAIRT 91                // upper-tri tile pairs
#define NCOMBO 273               // 91 * 3 d
#define EPSF   1e-6f
#define MULTF  0.0025f

// Self-resetting device state (zero-init at module load; finisher resets).
__device__ __align__(16) float g_G[3 * KP * KP];   // 8112 floats
__device__ float    g_out;
__device__ unsigned g_ctr1;
__device__ unsigned g_ctr2;

typedef unsigned long long ull;

__device__ __forceinline__ ull pack2(float a, float b) {
    ull r; asm("mov.b64 %0, {%1, %2};" : "=l"(r) : "f"(a), "f"(b)); return r;
}
__device__ __forceinline__ void unpack2(ull v, float& a, float& b) {
    asm("mov.b64 {%0, %1}, %2;" : "=f"(a), "=f"(b) : "l"(v));
}
__device__ __forceinline__ void ffma2(ull& d, ull a, ull b) {
    asm("fma.rn.f32x2 %0, %1, %2, %0;" : "+l"(d) : "l"(a), "l"(b));
}

__global__ void __launch_bounds__(256, 2)
fused_kernel(const float* __restrict__ bs,
             const float* __restrict__ y_hat,
             const float* __restrict__ y,
             float* __restrict__ out) {
    // Reused shared buffer:
    //   phase 1: As[3][COLS_D][CPAD] = 5376 floats
    //   phase 2: G_s (8112) + w_s (416) = 8528 floats  (34112 B, 2 CTAs/SM)
    __shared__ __align__(16) float smem[3 * KP * KP + 8 * KP];
    __shared__ bool s_last;

    const int tid = threadIdx.x;
    const int blk = blockIdx.x;

    // ======================= Phase 1: Gram =======================
    {
        const int c0 = blk * TCOLS;
        // Initial decode (tid < 256 -> k in {0,1,2}), then fully incremental.
        int k   = (tid >= 192) ? 2 : (tid >= 96 ? 1 : 0);
        int c   = tid - k * TCOLS;
        int d   = c % 3;
        int col = c / 3;
        const float* gp = bs + (size_t)k * CCOLS + c0 + c;

        // 51*96 = 4896 elements, stride 256: c += 64 (d += 1, col += 21), k += 2,
        // wrap c -= 96 (col -= 32), k += 1.   (256 = 2*96 + 64; 64 = 21*3 + 1)
        for (int idx = tid; idx < KDIM * TCOLS; idx += 256) {
            smem[(d * COLS_D + col) * CPAD + k] = __ldg(gp);
            gp += 2 * (size_t)CCOLS + 64;
            k += 2; c += 64; d += 1; col += 21;
            if (d == 3) { d = 0; col += 1; }
            if (c >= TCOLS) {
                c -= TCOLS; col -= COLS_D; k += 1;
                gp += (size_t)CCOLS - TCOLS;
            }
        }
        // Ones row (k = 51): carries EPS cross & square terms exactly.
        if (tid < TCOLS) {
            int dd = tid % 3, cc = tid / 3;
            smem[(dd * COLS_D + cc) * CPAD + KDIM] = 1.0f;
        }
        __syncthreads();

        // 273 combos; tids 0..16 take a second one.
        for (int combo = tid; combo < NCOMBO; combo += 256) {
            int d2   = combo / NPAIRT;
            int tile = combo - d2 * NPAIRT;
            int ti = 0, rem = tile;
            while (rem >= NTILE - ti) { rem -= NTILE - ti; ti++; }
            int tj = ti + rem;  // ti <= tj

            // Packed accumulators: acc2[p][s] = (acc[2p][s], acc[2p+1][s])
            ull acc2[2][4];
#pragma unroll
            for (int p = 0; p < 2; p++)
#pragma unroll
                for (int s = 0; s < 4; s++) acc2[p][s] = 0ull;

            const float* base = smem + d2 * COLS_D * CPAD;
#pragma unroll 8
            for (int col2 = 0; col2 < COLS_D; col2++) {
                longlong2 a = *reinterpret_cast<const longlong2*>(
                    base + col2 * CPAD + ti * 4);        // (a0,a1),(a2,a3) packed
                float4 b = *reinterpret_cast<const float4*>(
                    base + col2 * CPAD + tj * 4);
                ull bx = pack2(b.x, b.x), by = pack2(b.y, b.y);
                ull bz = pack2(b.z, b.z), bw = pack2(b.w, b.w);
                ffma2(acc2[0][0], (ull)a.x, bx);
                ffma2(acc2[0][1], (ull)a.x, by);
                ffma2(acc2[0][2], (ull)a.x, bz);
                ffma2(acc2[0][3], (ull)a.x, bw);
                ffma2(acc2[1][0], (ull)a.y, bx);
                ffma2(acc2[1][1], (ull)a.y, by);
                ffma2(acc2[1][2], (ull)a.y, bz);
                ffma2(acc2[1][3], (ull)a.y, bw);
            }

            // Unpack and reduce: row r -> G[d2][4ti+r][4tj..4tj+3].
#pragma unroll
            for (int p = 0; p < 2; p++) {
                float r0x, r1x, r0y, r1y, r0z, r1z, r0w, r1w;
                unpack2(acc2[p][0], r0x, r1x);
                unpack2(acc2[p][1], r0y, r1y);
                unpack2(acc2[p][2], r0z, r1z);
                unpack2(acc2[p][3], r0w, r1w);
                float4 v0 = make_float4(r0x, r0y, r0z, r0w);
                float4 v1 = make_float4(r1x, r1y, r1z, r1w);
                int r0 = ti * 4 + 2 * p;
                atomicAdd(reinterpret_cast<float4*>(
                              &g_G[d2 * KP * KP + r0 * KP + tj * 4]), v0);
                atomicAdd(reinterpret_cast<float4*>(
                              &g_G[d2 * KP * KP + (r0 + 1) * KP + tj * 4]), v1);
            }
        }
    }
    __syncthreads();
    if (tid == 0) {
        __threadfence();
        atomicAdd(&g_ctr1, 1u);
    }

    if (blk >= QBLKS) return;

    // Grid-wide barrier: wait for all 256 gram blocks (all co-resident @ occ 2).
    if (tid == 0) {
        while (atomicAdd(&g_ctr1, 0u) < (unsigned)GBLKS) { }
    }
    __syncthreads();

    // ======================= Phase 2: Quad =======================
    float* G_s = smem;                 // 8112 floats
    float* w_s = smem + 3 * KP * KP;   // 8 * KP floats

    for (int i = tid; i < 3 * KP * KP; i += 256) G_s[i] = __ldcg(&g_G[i]);
    const int b0 = blk * 8;
    for (int i = tid; i < 8 * KP; i += 256) {
        int bl = i / KP, k = i - bl * KP;
        w_s[bl * KP + k] = (k < KDIM)
            ? __ldg(&y_hat[(b0 + bl) * KDIM + k]) - __ldg(&y[(b0 + bl) * KDIM + k])
            : EPSF;
    }
    __syncthreads();

    const int wid  = tid >> 5;
    const int lane = tid & 31;
    const int k1   = lane;
    const int k2v  = lane + 32;
    const bool has2 = (k2v < KP);
    const int k2   = has2 ? k2v : KDIM;

    const float* w = w_s + wid * KP;
    const float wk1 = w[k1];
    const float wk2 = has2 ? w[k2v] : 0.0f;

    float total = 0.0f;
    for (int d = 0; d < 3; d++) {
        const float* G = G_s + d * KP * KP;
        float t1 = 0.0f, t2 = 0.0f;
#pragma unroll 4
        for (int k = 0; k < KP; k++) {
            float wk = w[k];
            float g1 = G[k * KP + k1];
            float g2 = G[k * KP + k2];
            float f1 = (k < k1)  ? wk : ((k == k1)  ? 0.5f * wk : 0.0f);
            float f2 = (k < k2v) ? wk : ((k == k2v) ? 0.5f * wk : 0.0f);
            t1 += g1 * f1;
            t2 += g2 * f2;
        }
        float p = 2.0f * (wk1 * t1 + wk2 * t2);
#pragma unroll
        for (int o = 16; o > 0; o >>= 1)
            p += __shfl_down_sync(0xFFFFFFFFu, p, o);
        if (lane == 0) total += sqrtf(p);
    }
    if (lane == 0) atomicAdd(&g_out, total);

    // ======================= Finisher =======================
    __syncthreads();
    if (tid == 0) {
        __threadfence();
        unsigned old = atomicAdd(&g_ctr2, 1u);
        s_last = (old == (unsigned)(QBLKS - 1));
    }
    __syncthreads();
    if (!s_last) return;

    if (tid == 0) {
        float v = atomicAdd(&g_out, 0.0f);
        out[0] = v * MULTF;
    }
    for (int i = tid; i < 3 * KP * KP; i += 256) g_G[i] = 0.0f;
    if (tid == 0) {
        g_out  = 0.0f;
        g_ctr1 = 0u;
        g_ctr2 = 0u;
    }
}

extern "C" void kernel_launch(void* const* d_in, const int* in_sizes, int n_in,
                              void* d_out, int out_size) {
    const float* y_hat = (const float*)d_in[0];  // [256, 51]
    const float* y     = (const float*)d_in[1];  // [256, 51]
    // d_in[2] = face — cancels out of the loss, unused
    const float* bs    = (const float*)d_in[3];  // [51, 8192, 3]
    float* out = (float*)d_out;

    fused_kernel<<<GBLKS, 256>>>(bs, y_hat, y, out);
}

// round 7
// speedup vs baseline: 1.0111x; 1.0111x over previous
#include <cuda_runtime.h>

// Fixed shapes
#define KDIM   51
#define KP     52                // padded K (row 51 = ones, carries EPS exactly)
#define BDIM   256
#define CCOLS  24576             // 8192 points * 3
#define TCOLS  384               // columns per gram block (128 per d)
#define GBLKS  64                // gram blocks (1/SM, all co-resident)
#define QBLKS  32                // blocks that continue into the quad phase
#define NTHR   288               // 9 warps; 273 combos -> <=1 per thread
#define COLS_D 128               // columns per d per block
#define CPAD   56                // padded k-extent (multiple of 4 for LDS.128)
#define NTILE  13                // 52/4 k-tiles
#define NPAIRT 91                // upper-tri tile pairs
#define NCOMBO 273               // 91 * 3 d
#define EPSF   1e-6f
#define MULTF  0.0025f

#define SMEM_FLOATS (3 * COLS_D * CPAD)        // 21504 floats = 86016 B
#define SMEM_BYTES  (SMEM_FLOATS * 4)

// Self-resetting device state (zero-init at module load; finisher resets).
__device__ __align__(16) float g_G[3 * KP * KP];   // 8112 floats
__device__ float    g_out;
__device__ unsigned g_ctr1;
__device__ unsigned g_ctr2;

typedef unsigned long long ull;

__device__ __forceinline__ ull pack2(float a, float b) {
    ull r; asm("mov.b64 %0, {%1, %2};" : "=l"(r) : "f"(a), "f"(b)); return r;
}
__device__ __forceinline__ void unpack2(ull v, float& a, float& b) {
    asm("mov.b64 {%0, %1}, %2;" : "=f"(a), "=f"(b) : "l"(v));
}
__device__ __forceinline__ void ffma2(ull& d, ull a, ull b) {
    asm("fma.rn.f32x2 %0, %1, %2, %0;" : "+l"(d) : "l"(a), "l"(b));
}

__global__ void __launch_bounds__(NTHR, 1)
fused_kernel(const float* __restrict__ bs,
             const float* __restrict__ y_hat,
             const float* __restrict__ y,
             float* __restrict__ out) {
    extern __shared__ __align__(16) float smem[];
    __shared__ bool s_last;

    const int tid = threadIdx.x;
    const int blk = blockIdx.x;

    // ======================= Phase 1: Gram =======================
    {
        const int c0 = blk * TCOLS;
        // Load 51 rows x 384 cols as float4, de-interleave by d = c%3.
        // 4896 float4s over 288 threads (17 per thread).
        for (int v = tid; v < KDIM * (TCOLS / 4); v += NTHR) {
            int k = v / (TCOLS / 4);
            int q = v - k * (TCOLS / 4);
            float4 val = *reinterpret_cast<const float4*>(
                bs + (size_t)k * CCOLS + c0 + q * 4);
            int c = q * 4;
#pragma unroll
            for (int j = 0; j < 4; j++) {
                int cj = c + j;
                int d = cj % 3, col = cj / 3;
                float x = (j == 0) ? val.x : (j == 1) ? val.y
                        : (j == 2) ? val.z : val.w;
                smem[(d * COLS_D + col) * CPAD + k] = x;
            }
        }
        // Ones row (k = 51): carries EPS cross & square terms exactly.
        for (int idx = tid; idx < TCOLS; idx += NTHR) {
            int d = idx % 3, col = idx / 3;
            smem[(d * COLS_D + col) * CPAD + KDIM] = 1.0f;
        }
        __syncthreads();

        // <=1 combo per thread; staggered per-block so concurrent blocks
        // emit atomics to different G slots (101 coprime to 273).
        if (tid < NCOMBO) {
            int combo = tid + blk * 101;
            combo -= (combo >= NCOMBO) ? NCOMBO : 0;
            combo -= (combo >= NCOMBO) ? NCOMBO : 0;  // blk*101 < 2*273*? safe: 63*101=6363
            combo = combo % NCOMBO;                   // (cheap; executed once)

            int d2   = combo / NPAIRT;
            int tile = combo - d2 * NPAIRT;
            int ti = 0, rem = tile;
            while (rem >= NTILE - ti) { rem -= NTILE - ti; ti++; }
            int tj = ti + rem;  // ti <= tj

            // Packed accumulators: acc2[p][s] = (acc[2p][s], acc[2p+1][s])
            ull acc2[2][4];
#pragma unroll
            for (int p = 0; p < 2; p++)
#pragma unroll
                for (int s = 0; s < 4; s++) acc2[p][s] = 0ull;

            const float* base = smem + d2 * COLS_D * CPAD;
#pragma unroll 8
            for (int col2 = 0; col2 < COLS_D; col2++) {
                longlong2 a = *reinterpret_cast<const longlong2*>(
                    base + col2 * CPAD + ti * 4);   // (a0,a1),(a2,a3) packed
                float4 b = *reinterpret_cast<const float4*>(
                    base + col2 * CPAD + tj * 4);
                ull bx = pack2(b.x, b.x), by = pack2(b.y, b.y);
                ull bz = pack2(b.z, b.z), bw = pack2(b.w, b.w);
                ffma2(acc2[0][0], (ull)a.x, bx);
                ffma2(acc2[0][1], (ull)a.x, by);
                ffma2(acc2[0][2], (ull)a.x, bz);
                ffma2(acc2[0][3], (ull)a.x, bw);
                ffma2(acc2[1][0], (ull)a.y, bx);
                ffma2(acc2[1][1], (ull)a.y, by);
                ffma2(acc2[1][2], (ull)a.y, bz);
                ffma2(acc2[1][3], (ull)a.y, bw);
            }

            // One vector RED per row: G[d2][4ti+r][4tj..4tj+3].
#pragma unroll
            for (int p = 0; p < 2; p++) {
                float r0x, r1x, r0y, r1y, r0z, r1z, r0w, r1w;
                unpack2(acc2[p][0], r0x, r1x);
                unpack2(acc2[p][1], r0y, r1y);
                unpack2(acc2[p][2], r0z, r1z);
                unpack2(acc2[p][3], r0w, r1w);
                float4 v0 = make_float4(r0x, r0y, r0z, r0w);
                float4 v1 = make_float4(r1x, r1y, r1z, r1w);
                int r0 = ti * 4 + 2 * p;
                atomicAdd(reinterpret_cast<float4*>(
                              &g_G[d2 * KP * KP + r0 * KP + tj * 4]), v0);
                atomicAdd(reinterpret_cast<float4*>(
                              &g_G[d2 * KP * KP + (r0 + 1) * KP + tj * 4]), v1);
            }
        }
    }
    __syncthreads();
    if (tid == 0) {
        __threadfence();
        atomicAdd(&g_ctr1, 1u);
    }

    if (blk >= QBLKS) return;

    // Grid-wide barrier: all 64 gram blocks are co-resident (1/SM).
    if (tid == 0) {
        while (atomicAdd(&g_ctr1, 0u) < (unsigned)GBLKS) { }
    }
    __syncthreads();

    // ======================= Phase 2: Quad =======================
    float* G_s = smem;                 // 8112 floats
    float* w_s = smem + 3 * KP * KP;   // 8 * KP floats

    for (int i = tid; i < 3 * KP * KP; i += NTHR) G_s[i] = __ldcg(&g_G[i]);
    const int b0 = blk * 8;
    for (int i = tid; i < 8 * KP; i += NTHR) {
        int bl = i / KP, k = i - bl * KP;
        w_s[bl * KP + k] = (k < KDIM)
            ? __ldg(&y_hat[(b0 + bl) * KDIM + k]) - __ldg(&y[(b0 + bl) * KDIM + k])
            : EPSF;
    }
    __syncthreads();

    const int wid  = tid >> 5;
    const int lane = tid & 31;

    if (wid < 8) {
        const int k1   = lane;
        const int k2v  = lane + 32;
        const bool has2 = (k2v < KP);
        const int k2   = has2 ? k2v : KDIM;

        const float* w = w_s + wid * KP;
        const float wk1 = w[k1];
        const float wk2 = has2 ? w[k2v] : 0.0f;

        float total = 0.0f;
        for (int d = 0; d < 3; d++) {
            const float* G = G_s + d * KP * KP;
            float t1 = 0.0f, t2 = 0.0f;
#pragma unroll 4
            for (int k = 0; k < KP; k++) {
                float wk = w[k];
                float g1 = G[k * KP + k1];
                float g2 = G[k * KP + k2];
                float f1 = (k < k1)  ? wk : ((k == k1)  ? 0.5f * wk : 0.0f);
                float f2 = (k < k2v) ? wk : ((k == k2v) ? 0.5f * wk : 0.0f);
                t1 += g1 * f1;
                t2 += g2 * f2;
            }
            float p = 2.0f * (wk1 * t1 + wk2 * t2);
#pragma unroll
            for (int o = 16; o > 0; o >>= 1)
                p += __shfl_down_sync(0xFFFFFFFFu, p, o);
            if (lane == 0) total += sqrtf(p);
        }
        if (lane == 0) atomicAdd(&g_out, total);
    }

    // ======================= Finisher =======================
    __syncthreads();
    if (tid == 0) {
        __threadfence();
        unsigned old = atomicAdd(&g_ctr2, 1u);
        s_last = (old == (unsigned)(QBLKS - 1));
    }
    __syncthreads();
    if (!s_last) return;

    if (tid == 0) {
        float v = atomicAdd(&g_out, 0.0f);
        out[0] = v * MULTF;
    }
    for (int i = tid; i < 3 * KP * KP; i += NTHR) g_G[i] = 0.0f;
    if (tid == 0) {
        g_out  = 0.0f;
        g_ctr1 = 0u;
        g_ctr2 = 0u;
    }
}

extern "C" void kernel_launch(void* const* d_in, const int* in_sizes, int n_in,
                              void* d_out, int out_size) {
    const float* y_hat = (const float*)d_in[0];  // [256, 51]
    const float* y     = (const float*)d_in[1];  // [256, 51]
    // d_in[2] = face — cancels out of the loss, unused
    const float* bs    = (const float*)d_in[3];  // [51, 8192, 3]
    float* out = (float*)d_out;

    static bool attr_set = false;
    if (!attr_set) {
        cudaFuncSetAttribute(fused_kernel,
                             cudaFuncAttributeMaxDynamicSharedMemorySize,
                             SMEM_BYTES);
        attr_set = true;
    }

    fused_kernel<<<GBLKS, NTHR, SMEM_BYTES>>>(bs, y_hat, y, out);
}

// round 8
// speedup vs baseline: 1.3788x; 1.3636x over previous
#include <cuda_runtime.h>

// Fixed shapes
#define KDIM   51
#define KP     52                // padded K (row 51 = ones, carries EPS exactly)
#define BDIM   256
#define CCOLS  24576             // 8192 points * 3
#define TCOLS  192               // columns per gram block (64 per d)
#define GBLKS  128               // gram blocks (1/SM, all co-resident)
#define QBLKS  32                // blocks that continue into the quad phase
#define NTHR   288               // 9 warps; 273 combos -> <=1 per thread
#define COLS_D 64                // columns per d per block
#define CPAD   56                // padded k-extent (multiple of 4 for LDS.128)
#define NTILE  13                // 52/4 k-tiles
#define NPAIRT 91                // upper-tri tile pairs
#define NCOMBO 273               // 91 * 3 d
#define NV4    (KDIM * TCOLS / 4)  // 2448 float4 loads per block
#define NLOAD  9                   // ceil(2448 / 288)
#define EPSF   1e-6f
#define MULTF  0.0025f

// Self-resetting device state (zero-init at module load; finisher resets).
__device__ __align__(16) float g_G[3 * KP * KP];   // 8112 floats
__device__ float    g_out;
__device__ unsigned g_ctr1;
__device__ unsigned g_ctr2;

typedef unsigned long long ull;

__device__ __forceinline__ ull pack2(float a, float b) {
    ull r; asm("mov.b64 %0, {%1, %2};" : "=l"(r) : "f"(a), "f"(b)); return r;
}
__device__ __forceinline__ void unpack2(ull v, float& a, float& b) {
    asm("mov.b64 {%0, %1}, %2;" : "=f"(a), "=f"(b) : "l"(v));
}
__device__ __forceinline__ void ffma2(ull& d, ull a, ull b) {
    asm("fma.rn.f32x2 %0, %1, %2, %0;" : "+l"(d) : "l"(a), "l"(b));
}

__global__ void __launch_bounds__(NTHR, 1)
fused_kernel(const float* __restrict__ bs,
             const float* __restrict__ y_hat,
             const float* __restrict__ y,
             float* __restrict__ out) {
    // Phase 1: As[3][COLS_D][CPAD] = 10752 floats (43008 B)
    // Phase 2 (same buffer): G_s (8112 floats) + w_s (416 floats)
    __shared__ __align__(16) float smem[3 * COLS_D * CPAD];
    __shared__ bool s_last;

    const int tid = threadIdx.x;
    const int blk = blockIdx.x;

    // ---- Prefetch w operands for quad blocks (latency hidden by phase 1) ----
    float wpre[2];
    int   widx[2];
    const bool is_quad = (blk < QBLKS);
#pragma unroll
    for (int j = 0; j < 2; j++) {
        int i = tid + j * NTHR;            // 0..575, need < 416
        widx[j] = i;
        wpre[j] = EPSF;
        if (is_quad && i < 8 * KP) {
            int bl = i / KP, k = i - bl * KP;
            if (k < KDIM) {
                int gi = (blk * 8 + bl) * KDIM + k;
                wpre[j] = __ldg(&y_hat[gi]) - __ldg(&y[gi]);
            }
        }
    }

    // ======================= Phase 1: Gram =======================
    {
        const int c0 = blk * TCOLS;
        // Front-batched loads: 9 independent LDG.128 per thread (MLP ~9).
        float4 vals[NLOAD];
        int    vv[NLOAD];
#pragma unroll
        for (int i = 0; i < NLOAD; i++) {
            int v = tid + i * NTHR;
            vv[i] = v;
            if (v < NV4) {
                int k = v / 48;            // 48 float4 per row
                int q = v - k * 48;
                vals[i] = *reinterpret_cast<const float4*>(
                    bs + (size_t)k * CCOLS + c0 + q * 4);
            }
        }
        // De-interleave stores: c = q*4 + j; d=(c)%3, col=(c)/3.
        // q*4 % 3 == q % 3, q*4/3 = q + (q - q%3)/3 = q + (q/3)... use direct:
#pragma unroll
        for (int i = 0; i < NLOAD; i++) {
            if (vv[i] < NV4) {
                int k  = vv[i] / 48;
                int q  = vv[i] - k * 48;
                int c  = q * 4;
                int q3 = c % 3;            // div-by-const, cheap
                int qc = c / 3;
                float x[4] = {vals[i].x, vals[i].y, vals[i].z, vals[i].w};
#pragma unroll
                for (int j = 0; j < 4; j++) {
                    int t   = q3 + j;              // 0..5
                    int add = (t >= 3) ? 1 : 0;
                    int d   = t - 3 * add;
                    int col = qc + add;
                    smem[(d * COLS_D + col) * CPAD + k] = x[j];
                }
            }
        }
        // Ones row (k = 51): carries EPS cross & square terms exactly.
        if (tid < TCOLS) {
            int d = tid % 3, col = tid / 3;
            smem[(d * COLS_D + col) * CPAD + KDIM] = 1.0f;
        }
        __syncthreads();

        // <=1 combo per thread, staggered across blocks (37 coprime to 273).
        if (tid < NCOMBO) {
            int combo = (tid + blk * 37) % NCOMBO;
            int d2   = combo / NPAIRT;
            int tile = combo - d2 * NPAIRT;
            int ti = 0, rem = tile;
            while (rem >= NTILE - ti) { rem -= NTILE - ti; ti++; }
            int tj = ti + rem;  // ti <= tj

            ull acc2[2][4];
#pragma unroll
            for (int p = 0; p < 2; p++)
#pragma unroll
                for (int s = 0; s < 4; s++) acc2[p][s] = 0ull;

            const float* base = smem + d2 * COLS_D * CPAD;
#pragma unroll 8
            for (int col2 = 0; col2 < COLS_D; col2++) {
                longlong2 a = *reinterpret_cast<const longlong2*>(
                    base + col2 * CPAD + ti * 4);
                float4 b = *reinterpret_cast<const float4*>(
                    base + col2 * CPAD + tj * 4);
                ull bx = pack2(b.x, b.x), by = pack2(b.y, b.y);
                ull bz = pack2(b.z, b.z), bw = pack2(b.w, b.w);
                ffma2(acc2[0][0], (ull)a.x, bx);
                ffma2(acc2[0][1], (ull)a.x, by);
                ffma2(acc2[0][2], (ull)a.x, bz);
                ffma2(acc2[0][3], (ull)a.x, bw);
                ffma2(acc2[1][0], (ull)a.y, bx);
                ffma2(acc2[1][1], (ull)a.y, by);
                ffma2(acc2[1][2], (ull)a.y, bz);
                ffma2(acc2[1][3], (ull)a.y, bw);
            }

#pragma unroll
            for (int p = 0; p < 2; p++) {
                float r0x, r1x, r0y, r1y, r0z, r1z, r0w, r1w;
                unpack2(acc2[p][0], r0x, r1x);
                unpack2(acc2[p][1], r0y, r1y);
                unpack2(acc2[p][2], r0z, r1z);
                unpack2(acc2[p][3], r0w, r1w);
                float4 v0 = make_float4(r0x, r0y, r0z, r0w);
                float4 v1 = make_float4(r1x, r1y, r1z, r1w);
                int r0 = ti * 4 + 2 * p;
                atomicAdd(reinterpret_cast<float4*>(
                              &g_G[d2 * KP * KP + r0 * KP + tj * 4]), v0);
                atomicAdd(reinterpret_cast<float4*>(
                              &g_G[d2 * KP * KP + (r0 + 1) * KP + tj * 4]), v1);
            }
        }
    }
    __syncthreads();   // all LDS of As done -> safe to repurpose smem
    if (tid == 0) {
        __threadfence();
        atomicAdd(&g_ctr1, 1u);
    }

    if (!is_quad) return;

    // Stash prefetched w into the w_s slot while waiting is set up.
    float* G_s = smem;                 // 8112 floats
    float* w_s = smem + 3 * KP * KP;   // 416 floats
#pragma unroll
    for (int j = 0; j < 2; j++)
        if (widx[j] < 8 * KP) w_s[widx[j]] = wpre[j];

    // Grid-wide barrier: all 128 gram blocks are co-resident (1/SM).
    if (tid == 0) {
        while (atomicAdd(&g_ctr1, 0u) < (unsigned)GBLKS) { }
    }
    __syncthreads();

    // ======================= Phase 2: Quad =======================
    // Batched vector reload of G (8x float4 per thread, MLP 8).
    {
        float4 gv[8];
        int    gi[8];
#pragma unroll
        for (int i = 0; i < 8; i++) {
            int v = tid + i * NTHR;        // < 2304; need < 2028
            gi[i] = v;
            if (v < (3 * KP * KP) / 4)
                gv[i] = __ldcg(reinterpret_cast<const float4*>(g_G) + v);
        }
#pragma unroll
        for (int i = 0; i < 8; i++)
            if (gi[i] < (3 * KP * KP) / 4)
                reinterpret_cast<float4*>(G_s)[gi[i]] = gv[i];
    }
    __syncthreads();

    const int wid  = tid >> 5;
    const int lane = tid & 31;

    if (wid < 8) {
        const int k1   = lane;
        const int k2v  = lane + 32;
        const bool has2 = (k2v < KP);
        const int k2   = has2 ? k2v : KDIM;

        const float* w = w_s + wid * KP;
        const float wk1 = w[k1];
        const float wk2 = has2 ? w[k2v] : 0.0f;

        float total = 0.0f;
        for (int d = 0; d < 3; d++) {
            const float* G = G_s + d * KP * KP;
            float t1 = 0.0f, t2 = 0.0f;
#pragma unroll 4
            for (int k = 0; k < KP; k++) {
                float wk = w[k];
                float g1 = G[k * KP + k1];
                float g2 = G[k * KP + k2];
                float f1 = (k < k1)  ? wk : ((k == k1)  ? 0.5f * wk : 0.0f);
                float f2 = (k < k2v) ? wk : ((k == k2v) ? 0.5f * wk : 0.0f);
                t1 += g1 * f1;
                t2 += g2 * f2;
            }
            float p = 2.0f * (wk1 * t1 + wk2 * t2);
#pragma unroll
            for (int o = 16; o > 0; o >>= 1)
                p += __shfl_down_sync(0xFFFFFFFFu, p, o);
            if (lane == 0) total += sqrtf(p);
        }
        if (lane == 0) atomicAdd(&g_out, total);
    }

    // ======================= Finisher =======================
    __syncthreads();
    if (tid == 0) {
        __threadfence();
        unsigned old = atomicAdd(&g_ctr2, 1u);
        s_last = (old == (unsigned)(QBLKS - 1));
    }
    __syncthreads();
    if (!s_last) return;

    if (tid == 0) {
        float v = atomicAdd(&g_out, 0.0f);
        out[0] = v * MULTF;
    }
    for (int i = tid; i < 3 * KP * KP; i += NTHR) g_G[i] = 0.0f;
    if (tid == 0) {
        g_out  = 0.0f;
        g_ctr1 = 0u;
        g_ctr2 = 0u;
    }
}

extern "C" void kernel_launch(void* const* d_in, const int* in_sizes, int n_in,
                              void* d_out, int out_size) {
    const float* y_hat = (const float*)d_in[0];  // [256, 51]
    const float* y     = (const float*)d_in[1];  // [256, 51]
    // d_in[2] = face — cancels out of the loss, unused
    const float* bs    = (const float*)d_in[3];  // [51, 8192, 3]
    float* out = (float*)d_out;

    fused_kernel<<<GBLKS, NTHR>>>(bs, y_hat, y, out);
}